// round 8
// baseline (speedup 1.0000x reference)
#include <cuda_runtime.h>
#include <cuda_bf16.h>
#include <cstddef>
#include <cstdint>

// Depthwise cross-correlation, persistent CTAs + cp.async double-buffered
// pipeline + channel-paired fp32x2 FMA.
//   out[ch, oy, ox] = sum_{ky,kx} x[ch, oy+ky, ox+kx] * z[ch, ky, kx]
//   32768 channels, x: 31x31, z: 7x7, out: 25x25 (VALID, no flip)
//
// R6 diagnosis: R4/R5 were memory-LATENCY bound (dur*BW == bytes moved, HBM
// at 22% of peak): staging and compute alternated with nothing in flight.
// R6: grid = 152 persistent CTAs; while computing group i from SMEM buffer A,
// group i+1 streams into buffer B via cp.async (no LDG->STS reg dependency).

#define NCHAN   32768
#define NPAIR   16384
#define HX      31
#define HZ      7
#define HO      25
#define XSZ     961
#define ZSZ     49
#define OSZ     625
#define PPB     10              // channel-pairs per group (20 channels)
#define TPC     25              // threads per pair (one per output column)
#define THREADS 256
#define GRID    152             // persistent: one CTA per SM (GB300)
#define NGROUPS 1639            // 1638 full groups + 1 tail group of 4 pairs

#define GX_FLOATS (PPB * 2 * XSZ)   // 19220 floats per full group (76880 B, 16B-aligned)
#define GZ_FLOATS (PPB * 2 * ZSZ)   //   980 floats
#define GX_V4     (GX_FLOATS / 4)   //  4805
#define GZ_V4     (GZ_FLOATS / 4)   //   245
#define TAILX_V4  1922              // 4 pairs: 7688 floats / 4
#define TAILZ_V4  98                // 4 pairs:  392 floats / 4

__device__ __forceinline__ void ffma2(float2& d, const float2& a, const float2& b) {
    asm("fma.rn.f32x2 %0, %1, %2, %0;"
        : "+l"(reinterpret_cast<unsigned long long&>(d))
        : "l"(reinterpret_cast<const unsigned long long&>(a)),
          "l"(reinterpret_cast<const unsigned long long&>(b)));
}

__device__ __forceinline__ void cpasync16(uint32_t saddr, const void* gaddr) {
    asm volatile("cp.async.cg.shared.global [%0], [%1], 16;"
                 :: "r"(saddr), "l"(gaddr) : "memory");
}
#define CP_COMMIT() asm volatile("cp.async.commit_group;" ::: "memory")
#define CP_WAIT1()  asm volatile("cp.async.wait_group 1;" ::: "memory")
#define CP_WAIT0()  asm volatile("cp.async.wait_group 0;" ::: "memory")

__device__ __forceinline__ void prefetch_group(
    int g, float* xs, float* zs,
    const float* __restrict__ x, const float* __restrict__ z, int tid)
{
    const bool tail = (g == NGROUPS - 1);
    const int nxv = tail ? TAILX_V4 : GX_V4;
    const int nzv = tail ? TAILZ_V4 : GZ_V4;
    const float4* gx = reinterpret_cast<const float4*>(x) + (size_t)g * GX_V4;
    const float4* gz = reinterpret_cast<const float4*>(z) + (size_t)g * GZ_V4;
    const uint32_t sx = (uint32_t)__cvta_generic_to_shared(xs);
    const uint32_t sz = (uint32_t)__cvta_generic_to_shared(zs);
    for (int j = tid; j < nxv; j += THREADS)
        cpasync16(sx + (uint32_t)j * 16u, gx + j);
    for (int j = tid; j < nzv; j += THREADS)
        cpasync16(sz + (uint32_t)j * 16u, gz + j);
}

__device__ __forceinline__ void compute_group(
    int g, const float* __restrict__ xs, const float* __restrict__ zs,
    float* __restrict__ out, int lp, int tx)
{
    const int p = g * PPB + lp;
    if (lp >= PPB || p >= NPAIR) return;    // no syncs inside: safe divergence

    const float* x0 = xs + (2 * lp) * XSZ;  // even channel of the pair
    const float* x1 = x0 + XSZ;             // odd channel
    const float* z0 = zs + (2 * lp) * ZSZ;
    const float* z1 = z0 + ZSZ;

    // 49 packed taps in registers.
    float2 kk[ZSZ];
    #pragma unroll
    for (int j = 0; j < ZSZ; ++j) kk[j] = make_float2(z0[j], z1[j]);

    // Ring of 7 packed accumulators: at x-row r, output rows [r-6, r] live.
    float2 acc[HZ];
    #pragma unroll
    for (int i = 0; i < HZ; ++i) acc[i] = make_float2(0.0f, 0.0f);

    float* go0 = out + (size_t)(2 * p) * OSZ + tx;
    float* go1 = go0 + OSZ;

    #pragma unroll
    for (int r = 0; r < HX; ++r) {
        float2 xr[HZ];
        #pragma unroll
        for (int c = 0; c < HZ; ++c)
            xr[c] = make_float2(x0[r * HX + tx + c], x1[r * HX + tx + c]);

        #pragma unroll
        for (int ky = 0; ky < HZ; ++ky) {
            const int oy = r - ky;
            if (oy >= 0 && oy < HO) {
                const int slot = oy % HZ;          // const after unroll
                #pragma unroll
                for (int kx = 0; kx < HZ; ++kx)
                    ffma2(acc[slot], xr[kx], kk[ky * HZ + kx]);
            }
        }

        if (r >= HZ - 1) {                         // row r-6 complete
            const int oy   = r - (HZ - 1);
            const int slot = oy % HZ;
            go0[oy * HO] = acc[slot].x;
            go1[oy * HO] = acc[slot].y;
            acc[slot] = make_float2(0.0f, 0.0f);
        }
    }
}

__global__ __launch_bounds__(THREADS, 1)
void dwxcorr_pipe(const float* __restrict__ z,
                  const float* __restrict__ x,
                  float* __restrict__ out) {
    extern __shared__ float smem[];
    float* xb0 = smem;
    float* xb1 = smem + GX_FLOATS;
    float* zb0 = smem + 2 * GX_FLOATS;
    float* zb1 = zb0 + GZ_FLOATS;

    const int tid = threadIdx.x;
    const int lp  = tid / TPC;       // local pair 0..9 (>=10: copy-only lanes)
    const int tx  = tid - lp * TPC;  // output column 0..24

    int g = blockIdx.x;
    if (g < NGROUPS)
        prefetch_group(g, xb0, zb0, x, z, tid);
    CP_COMMIT();

    int i = 0;
    for (; g < NGROUPS; g += GRID, ++i) {
        float* xc = (i & 1) ? xb1 : xb0;
        float* zc = (i & 1) ? zb1 : zb0;
        float* xn = (i & 1) ? xb0 : xb1;
        float* zn = (i & 1) ? zb0 : zb1;

        const int gn = g + GRID;
        if (gn < NGROUPS) {
            prefetch_group(gn, xn, zn, x, z, tid);   // background fill
            CP_COMMIT();
            CP_WAIT1();                               // current group landed
        } else {
            CP_WAIT0();
        }
        __syncthreads();                              // data visible to all

        compute_group(g, xc, zc, out, lp, tx);

        __syncthreads();                              // done reading xc/zc
    }
}

extern "C" void kernel_launch(void* const* d_in, const int* in_sizes, int n_in,
                              void* d_out, int out_size) {
    // metadata order: d_in[0] = z_f [128,256,7,7], d_in[1] = x_f [128,256,31,31]
    const float* z = (const float*)d_in[0];
    const float* x = (const float*)d_in[1];
    float* out = (float*)d_out;

    const size_t smem = (size_t)(2 * GX_FLOATS + 2 * GZ_FLOATS) * sizeof(float); // 161600 B
    cudaFuncSetAttribute(dwxcorr_pipe,
                         cudaFuncAttributeMaxDynamicSharedMemorySize, (int)smem);
    dwxcorr_pipe<<<GRID, THREADS, smem>>>(z, x, out);
}

// round 9
// speedup vs baseline: 1.0025x; 1.0025x over previous
#include <cuda_runtime.h>
#include <cuda_bf16.h>
#include <cstddef>
#include <cstdint>

// Depthwise cross-correlation, persistent CTAs + cp.async double-buffered
// pipeline + channel-paired fp32x2 FMA.
//   out[ch, oy, ox] = sum_{ky,kx} x[ch, oy+ky, ox+kx] * z[ch, ky, kx]
//   32768 channels, x: 31x31, z: 7x7, out: 25x25 (VALID, no flip)
//
// R6 diagnosis: R4/R5 were memory-LATENCY bound (dur*BW == bytes moved, HBM
// at 22% of peak): staging and compute alternated with nothing in flight.
// R6: grid = 152 persistent CTAs; while computing group i from SMEM buffer A,
// group i+1 streams into buffer B via cp.async (no LDG->STS reg dependency).

#define NCHAN   32768
#define NPAIR   16384
#define HX      31
#define HZ      7
#define HO      25
#define XSZ     961
#define ZSZ     49
#define OSZ     625
#define PPB     10              // channel-pairs per group (20 channels)
#define TPC     25              // threads per pair (one per output column)
#define THREADS 256
#define GRID    152             // persistent: one CTA per SM (GB300)
#define NGROUPS 1639            // 1638 full groups + 1 tail group of 4 pairs

#define GX_FLOATS (PPB * 2 * XSZ)   // 19220 floats per full group (76880 B, 16B-aligned)
#define GZ_FLOATS (PPB * 2 * ZSZ)   //   980 floats
#define GX_V4     (GX_FLOATS / 4)   //  4805
#define GZ_V4     (GZ_FLOATS / 4)   //   245
#define TAILX_V4  1922              // 4 pairs: 7688 floats / 4
#define TAILZ_V4  98                // 4 pairs:  392 floats / 4

__device__ __forceinline__ void ffma2(float2& d, const float2& a, const float2& b) {
    asm("fma.rn.f32x2 %0, %1, %2, %0;"
        : "+l"(reinterpret_cast<unsigned long long&>(d))
        : "l"(reinterpret_cast<const unsigned long long&>(a)),
          "l"(reinterpret_cast<const unsigned long long&>(b)));
}

__device__ __forceinline__ void cpasync16(uint32_t saddr, const void* gaddr) {
    asm volatile("cp.async.cg.shared.global [%0], [%1], 16;"
                 :: "r"(saddr), "l"(gaddr) : "memory");
}
#define CP_COMMIT() asm volatile("cp.async.commit_group;" ::: "memory")
#define CP_WAIT1()  asm volatile("cp.async.wait_group 1;" ::: "memory")
#define CP_WAIT0()  asm volatile("cp.async.wait_group 0;" ::: "memory")

__device__ __forceinline__ void prefetch_group(
    int g, float* xs, float* zs,
    const float* __restrict__ x, const float* __restrict__ z, int tid)
{
    const bool tail = (g == NGROUPS - 1);
    const int nxv = tail ? TAILX_V4 : GX_V4;
    const int nzv = tail ? TAILZ_V4 : GZ_V4;
    const float4* gx = reinterpret_cast<const float4*>(x) + (size_t)g * GX_V4;
    const float4* gz = reinterpret_cast<const float4*>(z) + (size_t)g * GZ_V4;
    const uint32_t sx = (uint32_t)__cvta_generic_to_shared(xs);
    const uint32_t sz = (uint32_t)__cvta_generic_to_shared(zs);
    for (int j = tid; j < nxv; j += THREADS)
        cpasync16(sx + (uint32_t)j * 16u, gx + j);
    for (int j = tid; j < nzv; j += THREADS)
        cpasync16(sz + (uint32_t)j * 16u, gz + j);
}

__device__ __forceinline__ void compute_group(
    int g, const float* __restrict__ xs, const float* __restrict__ zs,
    float* __restrict__ out, int lp, int tx)
{
    const int p = g * PPB + lp;
    if (lp >= PPB || p >= NPAIR) return;    // no syncs inside: safe divergence

    const float* x0 = xs + (2 * lp) * XSZ;  // even channel of the pair
    const float* x1 = x0 + XSZ;             // odd channel
    const float* z0 = zs + (2 * lp) * ZSZ;
    const float* z1 = z0 + ZSZ;

    // 49 packed taps in registers.
    float2 kk[ZSZ];
    #pragma unroll
    for (int j = 0; j < ZSZ; ++j) kk[j] = make_float2(z0[j], z1[j]);

    // Ring of 7 packed accumulators: at x-row r, output rows [r-6, r] live.
    float2 acc[HZ];
    #pragma unroll
    for (int i = 0; i < HZ; ++i) acc[i] = make_float2(0.0f, 0.0f);

    float* go0 = out + (size_t)(2 * p) * OSZ + tx;
    float* go1 = go0 + OSZ;

    #pragma unroll
    for (int r = 0; r < HX; ++r) {
        float2 xr[HZ];
        #pragma unroll
        for (int c = 0; c < HZ; ++c)
            xr[c] = make_float2(x0[r * HX + tx + c], x1[r * HX + tx + c]);

        #pragma unroll
        for (int ky = 0; ky < HZ; ++ky) {
            const int oy = r - ky;
            if (oy >= 0 && oy < HO) {
                const int slot = oy % HZ;          // const after unroll
                #pragma unroll
                for (int kx = 0; kx < HZ; ++kx)
                    ffma2(acc[slot], xr[kx], kk[ky * HZ + kx]);
            }
        }

        if (r >= HZ - 1) {                         // row r-6 complete
            const int oy   = r - (HZ - 1);
            const int slot = oy % HZ;
            go0[oy * HO] = acc[slot].x;
            go1[oy * HO] = acc[slot].y;
            acc[slot] = make_float2(0.0f, 0.0f);
        }
    }
}

__global__ __launch_bounds__(THREADS, 1)
void dwxcorr_pipe(const float* __restrict__ z,
                  const float* __restrict__ x,
                  float* __restrict__ out) {
    extern __shared__ float smem[];
    float* xb0 = smem;
    float* xb1 = smem + GX_FLOATS;
    float* zb0 = smem + 2 * GX_FLOATS;
    float* zb1 = zb0 + GZ_FLOATS;

    const int tid = threadIdx.x;
    const int lp  = tid / TPC;       // local pair 0..9 (>=10: copy-only lanes)
    const int tx  = tid - lp * TPC;  // output column 0..24

    int g = blockIdx.x;
    if (g < NGROUPS)
        prefetch_group(g, xb0, zb0, x, z, tid);
    CP_COMMIT();

    int i = 0;
    for (; g < NGROUPS; g += GRID, ++i) {
        float* xc = (i & 1) ? xb1 : xb0;
        float* zc = (i & 1) ? zb1 : zb0;
        float* xn = (i & 1) ? xb0 : xb1;
        float* zn = (i & 1) ? zb0 : zb1;

        const int gn = g + GRID;
        if (gn < NGROUPS) {
            prefetch_group(gn, xn, zn, x, z, tid);   // background fill
            CP_COMMIT();
            CP_WAIT1();                               // current group landed
        } else {
            CP_WAIT0();
        }
        __syncthreads();                              // data visible to all

        compute_group(g, xc, zc, out, lp, tx);

        __syncthreads();                              // done reading xc/zc
    }
}

extern "C" void kernel_launch(void* const* d_in, const int* in_sizes, int n_in,
                              void* d_out, int out_size) {
    // metadata order: d_in[0] = z_f [128,256,7,7], d_in[1] = x_f [128,256,31,31]
    const float* z = (const float*)d_in[0];
    const float* x = (const float*)d_in[1];
    float* out = (float*)d_out;

    const size_t smem = (size_t)(2 * GX_FLOATS + 2 * GZ_FLOATS) * sizeof(float); // 161600 B
    cudaFuncSetAttribute(dwxcorr_pipe,
                         cudaFuncAttributeMaxDynamicSharedMemorySize, (int)smem);
    dwxcorr_pipe<<<GRID, THREADS, smem>>>(z, x, out);
}

// round 10
// speedup vs baseline: 1.2886x; 1.2854x over previous
#include <cuda_runtime.h>
#include <cuda_bf16.h>
#include <cstddef>
#include <cstdint>

// Depthwise cross-correlation — R10: kx-paired fp32x2 FMA, 2 CTAs/SM,
// persistent grid + cp.async double buffering.
//   out[ch, oy, ox] = sum_{ky,kx} x[ch, oy+ky, ox+kx] * z[ch, ky, kx]
//   32768 channels, x: 31x31, z: 7x7, out: 25x25 (VALID, no flip)
//
// f32x2 lanes = (even-kx partial, odd-kx partial) of ONE output; folded with
// one FADD at store. kx padded 7->8 with a zero tap, so both FFMA2 operands
// are memory-adjacent pairs (no repacking) and window overrun is harmless.

#define NCHAN   32768
#define HX      31
#define HZ      7
#define HO      25
#define XSZ     961
#define ZSZ     49
#define OSZ     625
#define CPG     8               // channels per group: 8*961 floats = 16B-multiple
#define TPC     25              // threads per channel (one per output column)
#define THREADS 256
#define CTAS_PER_SM 2
#define GRID    (152 * CTAS_PER_SM)
#define NGROUPS (NCHAN / CPG)   // 4096 exactly, no tail

#define GX_FLOATS (CPG * XSZ)       // 7688
#define GX_PAD    (GX_FLOATS + 8)   // slack for the last channel's window overrun
#define GZ_FLOATS (CPG * ZSZ)       // 392
#define GX_V4     (GX_FLOATS / 4)   // 1922
#define GZ_V4     (GZ_FLOATS / 4)   // 98

__device__ __forceinline__ void ffma2(float2& d, const float2& a, const float2& b) {
    asm("fma.rn.f32x2 %0, %1, %2, %0;"
        : "+l"(reinterpret_cast<unsigned long long&>(d))
        : "l"(reinterpret_cast<const unsigned long long&>(a)),
          "l"(reinterpret_cast<const unsigned long long&>(b)));
}

__device__ __forceinline__ void cpasync16(uint32_t saddr, const void* gaddr) {
    asm volatile("cp.async.cg.shared.global [%0], [%1], 16;"
                 :: "r"(saddr), "l"(gaddr) : "memory");
}
#define CP_COMMIT() asm volatile("cp.async.commit_group;" ::: "memory")
#define CP_WAIT1()  asm volatile("cp.async.wait_group 1;" ::: "memory")
#define CP_WAIT0()  asm volatile("cp.async.wait_group 0;" ::: "memory")

__device__ __forceinline__ void prefetch_group(
    int g, float* xs, float* zs,
    const float* __restrict__ x, const float* __restrict__ z, int tid)
{
    const float4* gx = reinterpret_cast<const float4*>(x) + (size_t)g * GX_V4;
    const float4* gz = reinterpret_cast<const float4*>(z) + (size_t)g * GZ_V4;
    const uint32_t sx = (uint32_t)__cvta_generic_to_shared(xs);
    const uint32_t sz = (uint32_t)__cvta_generic_to_shared(zs);
    #pragma unroll
    for (int j = tid; j < GX_V4; j += THREADS)      // 7-8 per thread
        cpasync16(sx + (uint32_t)j * 16u, gx + j);
    if (tid < GZ_V4)
        cpasync16(sz + (uint32_t)tid * 16u, gz + tid);
}

__device__ __forceinline__ void compute_group(
    int g, const float* __restrict__ xs, const float* __restrict__ zs,
    float* __restrict__ out, int lch, int tx)
{
    if (lch >= CPG) return;                  // copy-only lanes; no syncs inside

    const float* xc = xs + lch * XSZ;
    const float* zc = zs + lch * ZSZ;

    // Taps as kx pairs, kx padded to 8 with a zero column: 28 float2 (56 regs).
    float2 kt[HZ][4];
    #pragma unroll
    for (int ky = 0; ky < HZ; ++ky) {
        kt[ky][0] = make_float2(zc[7 * ky + 0], zc[7 * ky + 1]);
        kt[ky][1] = make_float2(zc[7 * ky + 2], zc[7 * ky + 3]);
        kt[ky][2] = make_float2(zc[7 * ky + 4], zc[7 * ky + 5]);
        kt[ky][3] = make_float2(zc[7 * ky + 6], 0.0f);
    }

    // Ring of 7 accumulator pairs (even/odd-kx partials of one output each).
    float2 acc[HZ];
    #pragma unroll
    for (int i = 0; i < HZ; ++i) acc[i] = make_float2(0.0f, 0.0f);

    const float* xb = xc + tx;
    float* go = out + (size_t)(g * CPG + lch) * OSZ + tx;

    #pragma unroll
    for (int r = 0; r < HX; ++r) {
        // 8-float window; w[7] only ever multiplies the zero tap.
        float w[8];
        #pragma unroll
        for (int c = 0; c < 8; ++c) w[c] = xb[r * HX + c];
        const float2 a0 = make_float2(w[0], w[1]);
        const float2 a1 = make_float2(w[2], w[3]);
        const float2 a2 = make_float2(w[4], w[5]);
        const float2 a3 = make_float2(w[6], w[7]);

        #pragma unroll
        for (int ky = 0; ky < HZ; ++ky) {
            const int oy = r - ky;
            if (oy >= 0 && oy < HO) {
                const int s = oy % HZ;        // compile-time after unroll
                ffma2(acc[s], a0, kt[ky][0]);
                ffma2(acc[s], a1, kt[ky][1]);
                ffma2(acc[s], a2, kt[ky][2]);
                ffma2(acc[s], a3, kt[ky][3]);
            }
        }

        if (r >= HZ - 1) {                    // output row r-6 complete
            const int oy = r - (HZ - 1);
            const int s  = oy % HZ;
            go[oy * HO] = acc[s].x + acc[s].y;   // fold even/odd-kx partials
            acc[s] = make_float2(0.0f, 0.0f);
        }
    }
}

__global__ __launch_bounds__(THREADS, CTAS_PER_SM)
void dwxcorr_kx2(const float* __restrict__ z,
                 const float* __restrict__ x,
                 float* __restrict__ out) {
    extern __shared__ float smem[];
    float* xb0 = smem;
    float* xb1 = smem + GX_PAD;
    float* zb0 = smem + 2 * GX_PAD;
    float* zb1 = zb0 + GZ_FLOATS;

    const int tid = threadIdx.x;
    const int lch = tid / TPC;        // local channel 0..7 (>=8: copy-only)
    const int tx  = tid - lch * TPC;  // output column 0..24

    int g = blockIdx.x;
    if (g < NGROUPS)
        prefetch_group(g, xb0, zb0, x, z, tid);
    CP_COMMIT();

    int i = 0;
    for (; g < NGROUPS; g += GRID, ++i) {
        float* xc = (i & 1) ? xb1 : xb0;
        float* zc = (i & 1) ? zb1 : zb0;
        float* xn = (i & 1) ? xb0 : xb1;
        float* zn = (i & 1) ? zb0 : zb1;

        const int gn = g + GRID;
        if (gn < NGROUPS) {
            prefetch_group(gn, xn, zn, x, z, tid);   // background fill
            CP_COMMIT();
            CP_WAIT1();                               // current group landed
        } else {
            CP_WAIT0();
        }
        __syncthreads();

        compute_group(g, xc, zc, out, lch, tx);

        __syncthreads();                              // done reading xc/zc
    }
}

extern "C" void kernel_launch(void* const* d_in, const int* in_sizes, int n_in,
                              void* d_out, int out_size) {
    // metadata order: d_in[0] = z_f [128,256,7,7], d_in[1] = x_f [128,256,31,31]
    const float* z = (const float*)d_in[0];
    const float* x = (const float*)d_in[1];
    float* out = (float*)d_out;

    const size_t smem = (size_t)(2 * GX_PAD + 2 * GZ_FLOATS) * sizeof(float); // 64704 B
    cudaFuncSetAttribute(dwxcorr_kx2,
                         cudaFuncAttributeMaxDynamicSharedMemorySize, (int)smem);
    dwxcorr_kx2<<<GRID, THREADS, smem>>>(z, x, out);
}